// round 1
// baseline (speedup 1.0000x reference)
#include <cuda_runtime.h>

#define H 4096
#define NIN 17
#define NA 4
#define TILE_C 8     // columns per block
#define TY 32        // row lanes
#define THREADS (TILE_C * TY)

// d_out layout (flatten of (activout[4], valueout[1], h[4096], hebb_new[4096*4096])):
//   [0..3] activout, [4] valueout, [5..5+H) h, [5+H ..) hebb_new

__global__ __launch_bounds__(THREADS, 1)
void fused_rnn_kernel(const float* __restrict__ x,
                      const float* __restrict__ hidden,
                      const float* __restrict__ hebb,
                      const float* __restrict__ i2h_w,
                      const float* __restrict__ i2h_b,
                      const float* __restrict__ w,
                      const float* __restrict__ alpha,
                      const float* __restrict__ eta,
                      float* __restrict__ out)
{
    extern __shared__ float sh[];
    float* sh_hebb   = sh;                          // H * TILE_C  (row-major, 8 cols)
    float* sh_hidden = sh_hebb + (size_t)H * TILE_C; // H
    float* sh_red    = sh_hidden + H;                // TY * TILE_C
    float* sh_h      = sh_red + TY * TILE_C;         // TILE_C

    const int tx  = threadIdx.x;             // 0..7  : column within tile
    const int ty  = threadIdx.y;             // 0..31 : row phase
    const int tid = ty * TILE_C + tx;
    const int j   = blockIdx.x * TILE_C + tx; // global column

    // cooperative load of hidden into smem (16 KiB)
    for (int i = tid; i < H; i += THREADS) sh_hidden[i] = hidden[i];
    __syncthreads();

    // ---- Phase 1: acc_j = sum_i hidden[i] * (w[i,j] + alpha[i,j]*hebb[i,j]) ----
    float acc0 = 0.f, acc1 = 0.f;
    #pragma unroll 8
    for (int k = 0; k < H / TY; ++k) {
        const int i = ty + k * TY;
        const size_t gidx = (size_t)i * H + j;
        const float hb = hebb[gidx];
        const float wv = w[gidx];
        const float av = alpha[gidx];
        sh_hebb[i * TILE_C + tx] = hb;          // stash for phase 2 (no DRAM re-read)
        const float t = sh_hidden[i] * fmaf(av, hb, wv);
        if (k & 1) acc1 += t; else acc0 += t;
    }
    sh_red[ty * TILE_C + tx] = acc0 + acc1;
    __syncthreads();

    // ---- column reduction + i2h + tanh (8 threads of row 0) ----
    if (ty == 0) {
        float s = 0.f;
        #pragma unroll
        for (int t = 0; t < TY; ++t) s += sh_red[t * TILE_C + tx];
        float pre = i2h_b[j];
        #pragma unroll
        for (int kk = 0; kk < NIN; ++kk) pre += x[kk] * i2h_w[j * NIN + kk];
        const float hj = tanhf(pre + s);
        sh_h[tx] = hj;
        out[5 + j] = hj;                         // publish h for the head kernel
    }
    __syncthreads();

    // ---- Phase 2: hebb_new[i,j] = (1-eta)*hebb[i,j] + eta*hidden[i]*h[j] ----
    const float eta_v = eta[0];
    const float om    = 1.f - eta_v;
    const float hj    = sh_h[tx];
    float* __restrict__ hebb_out = out + 5 + H;
    #pragma unroll 8
    for (int k = 0; k < H / TY; ++k) {
        const int i = ty + k * TY;
        const float hb = sh_hebb[i * TILE_C + tx];
        hebb_out[(size_t)i * H + j] = om * hb + eta_v * sh_hidden[i] * hj;
    }
}

// Tiny heads: activout = softmax(h @ h2o_w.T + h2o_b), valueout = h @ h2v_w.T + h2v_b
__global__ void head_kernel(const float* __restrict__ h,   // = out + 5
                            const float* __restrict__ h2o_w,
                            const float* __restrict__ h2o_b,
                            const float* __restrict__ h2v_w,
                            const float* __restrict__ h2v_b,
                            float* __restrict__ out)
{
    __shared__ float sh_logit[NA + 1];
    const int warp = threadIdx.x >> 5;
    const int lane = threadIdx.x & 31;
    if (warp < NA + 1) {
        const float* wrow = (warp < NA) ? (h2o_w + (size_t)warp * H) : h2v_w;
        float s = 0.f;
        for (int j = lane; j < H; j += 32) s += h[j] * wrow[j];
        #pragma unroll
        for (int o = 16; o; o >>= 1) s += __shfl_xor_sync(0xffffffffu, s, o);
        if (lane == 0)
            sh_logit[warp] = s + ((warp < NA) ? h2o_b[warp] : h2v_b[0]);
    }
    __syncthreads();
    if (threadIdx.x == 0) {
        float m = sh_logit[0];
        #pragma unroll
        for (int a = 1; a < NA; ++a) m = fmaxf(m, sh_logit[a]);
        float e[NA], se = 0.f;
        #pragma unroll
        for (int a = 0; a < NA; ++a) { e[a] = expf(sh_logit[a] - m); se += e[a]; }
        const float inv = 1.f / se;
        #pragma unroll
        for (int a = 0; a < NA; ++a) out[a] = e[a] * inv;
        out[NA] = sh_logit[NA];
    }
}

extern "C" void kernel_launch(void* const* d_in, const int* in_sizes, int n_in,
                              void* d_out, int out_size)
{
    const float* x      = (const float*)d_in[0];
    const float* hidden = (const float*)d_in[1];
    const float* hebb   = (const float*)d_in[2];
    const float* i2h_w  = (const float*)d_in[3];
    const float* i2h_b  = (const float*)d_in[4];
    const float* w      = (const float*)d_in[5];
    const float* alpha  = (const float*)d_in[6];
    const float* eta    = (const float*)d_in[7];
    const float* h2o_w  = (const float*)d_in[8];
    const float* h2o_b  = (const float*)d_in[9];
    const float* h2v_w  = (const float*)d_in[10];
    const float* h2v_b  = (const float*)d_in[11];
    float* out = (float*)d_out;

    const size_t smem = ((size_t)H * TILE_C + H + TY * TILE_C + TILE_C) * sizeof(float);
    static bool attr_set = false;
    // idempotent, cheap; not a stream op so safe under capture
    cudaFuncSetAttribute(fused_rnn_kernel,
                         cudaFuncAttributeMaxDynamicSharedMemorySize, (int)smem);
    (void)attr_set;

    dim3 blk(TILE_C, TY);
    fused_rnn_kernel<<<H / TILE_C, blk, smem>>>(x, hidden, hebb, i2h_w, i2h_b,
                                                w, alpha, eta, out);
    head_kernel<<<1, 32 * (NA + 1)>>>(out + 5, h2o_w, h2o_b, h2v_w, h2v_b, out);
}

// round 3
// speedup vs baseline: 1.3046x; 1.3046x over previous
#include <cuda_runtime.h>

#define H 4096
#define NIN 17
#define NA 4
#define TILE_C 8          // columns per block
#define THREADS 512       // 16 warps
#define ROWLANES 256      // THREADS/2 row lanes (2 col-quads each)
#define KITERS (H / ROWLANES)   // 16

// d_out layout: [0..3] activout, [4] valueout, [5..5+H) h, [5+H ..) hebb_new
// NOTE: hebb_new starts at float index 4101 -> every row misaligned by 4B.
// Loads from hebb/w/alpha are float4 (base-aligned); hebb_new stores are scalar.

__global__ __launch_bounds__(THREADS, 1)
void fused_rnn_kernel(const float* __restrict__ x,
                      const float* __restrict__ hidden,
                      const float* __restrict__ hebb,
                      const float* __restrict__ i2h_w,
                      const float* __restrict__ i2h_b,
                      const float* __restrict__ w,
                      const float* __restrict__ alpha,
                      const float* __restrict__ eta,
                      float* __restrict__ out)
{
    extern __shared__ float sh[];
    float*  sh_hebb   = sh;                                   // H*TILE_C floats (128 KiB), [i][col]
    float*  sh_hidden = sh_hebb + (size_t)H * TILE_C;         // H floats
    float4* sh_red    = (float4*)(sh_hidden + H);             // 32 float4
    float*  sh_h      = (float*)(sh_red + 32);                // 8 floats

    const int tid  = threadIdx.x;
    const int tx   = tid & 1;        // which float4-quad of the 8 columns
    const int r    = tid >> 1;       // 0..255 row lane
    const int warp = tid >> 5;
    const int lane = tid & 31;
    const int jbase = blockIdx.x * TILE_C;
    const int cquad = (jbase >> 2) + tx;   // float4 column index

    const float4* __restrict__ hebb4 = (const float4*)hebb;
    const float4* __restrict__ w4    = (const float4*)w;
    const float4* __restrict__ a4    = (const float4*)alpha;
    float4* sh_hebb4 = (float4*)sh_hebb;

    // cooperative load of hidden (16 KiB)
    for (int i = tid; i < H; i += THREADS) sh_hidden[i] = hidden[i];
    __syncthreads();

    // ---- Phase 1: per-column partial sums, stash hebb tile in smem ----
    float4 acc = make_float4(0.f, 0.f, 0.f, 0.f);
    #pragma unroll 4
    for (int k = 0; k < KITERS; ++k) {
        const int i = r + k * ROWLANES;
        const size_t gidx = (size_t)i * (H / 4) + cquad;
        const float4 hb = hebb4[gidx];
        const float4 wv = w4[gidx];
        const float4 av = a4[gidx];
        sh_hebb4[i * 2 + tx] = hb;              // stash: no DRAM re-read in phase 2
        const float hv = sh_hidden[i];
        acc.x = fmaf(hv, fmaf(av.x, hb.x, wv.x), acc.x);
        acc.y = fmaf(hv, fmaf(av.y, hb.y, wv.y), acc.y);
        acc.z = fmaf(hv, fmaf(av.z, hb.z, wv.z), acc.z);
        acc.w = fmaf(hv, fmaf(av.w, hb.w, wv.w), acc.w);
    }
    // reduce over row lanes within warp (xor 16,8,4,2 keeps tx bit 0 intact)
    #pragma unroll
    for (int o = 16; o >= 2; o >>= 1) {
        acc.x += __shfl_xor_sync(0xffffffffu, acc.x, o);
        acc.y += __shfl_xor_sync(0xffffffffu, acc.y, o);
        acc.z += __shfl_xor_sync(0xffffffffu, acc.z, o);
        acc.w += __shfl_xor_sync(0xffffffffu, acc.w, o);
    }
    if (lane < 2) sh_red[warp * 2 + lane] = acc;   // lane==tx here
    __syncthreads();

    // ---- final reduction across 16 warps + i2h + tanh (8 threads) ----
    if (tid < TILE_C) {
        const int g = tid >> 2;          // col-quad
        const int c = tid & 3;           // col within quad
        const float* red = (const float*)sh_red;
        float s = 0.f;
        #pragma unroll
        for (int wp = 0; wp < 16; ++wp) s += red[(wp * 2 + g) * 4 + c];
        const int j = jbase + tid;
        float pre = i2h_b[j];
        #pragma unroll
        for (int kk = 0; kk < NIN; ++kk) pre += x[kk] * i2h_w[j * NIN + kk];
        const float hj = tanhf(pre + s);
        sh_h[tid] = hj;
        out[5 + j] = hj;                 // publish h for the head kernel
    }
    __syncthreads();

    // ---- Phase 2: hebb_new = (1-eta)*hebb + eta * hidden (x) h ----
    // Remapped: lane = row*8 + col -> each warp STG covers 4 full 32B sectors.
    {
        const float eta_v = eta[0];
        const float om    = 1.f - eta_v;
        const int   c     = tid & 7;         // column within tile
        const int   rr    = tid >> 3;        // 0..63 row lane
        const float hj    = sh_h[c];
        float* __restrict__ hebb_out = out + 5 + H + jbase + c;
        #pragma unroll 8
        for (int k = 0; k < H / (THREADS / TILE_C); ++k) {   // 64 iters
            const int i = rr + k * (THREADS / TILE_C);
            const float hb = sh_hebb[i * TILE_C + c];
            hebb_out[(size_t)i * H] = fmaf(om, hb, eta_v * sh_hidden[i] * hj);
        }
    }
}

// Heads: activout = softmax(h @ h2o_w.T + h2o_b), valueout = h @ h2v_w.T + h2v_b
__global__ __launch_bounds__(1024)
void head_kernel(const float* __restrict__ h,   // = out + 5
                 const float* __restrict__ h2o_w,
                 const float* __restrict__ h2o_b,
                 const float* __restrict__ h2v_w,
                 const float* __restrict__ h2v_b,
                 float* __restrict__ out)
{
    __shared__ float red[32][NA + 1];
    __shared__ float logits[NA + 1];
    const int tid  = threadIdx.x;
    const int warp = tid >> 5;
    const int lane = tid & 31;

    float acc[NA + 1] = {0.f, 0.f, 0.f, 0.f, 0.f};
    #pragma unroll
    for (int k = 0; k < H / 1024; ++k) {
        const int j = tid + k * 1024;
        const float hv = h[j];
        acc[0] = fmaf(hv, h2o_w[0 * H + j], acc[0]);
        acc[1] = fmaf(hv, h2o_w[1 * H + j], acc[1]);
        acc[2] = fmaf(hv, h2o_w[2 * H + j], acc[2]);
        acc[3] = fmaf(hv, h2o_w[3 * H + j], acc[3]);
        acc[4] = fmaf(hv, h2v_w[j],         acc[4]);
    }
    #pragma unroll
    for (int a = 0; a < NA + 1; ++a) {
        #pragma unroll
        for (int o = 16; o; o >>= 1) acc[a] += __shfl_xor_sync(0xffffffffu, acc[a], o);
        if (lane == 0) red[warp][a] = acc[a];
    }
    __syncthreads();
    if (tid < NA + 1) {
        float s = (tid < NA) ? h2o_b[tid] : h2v_b[0];
        #pragma unroll
        for (int wp = 0; wp < 32; ++wp) s += red[wp][tid];
        logits[tid] = s;
    }
    __syncthreads();
    if (tid == 0) {
        float m = logits[0];
        #pragma unroll
        for (int a = 1; a < NA; ++a) m = fmaxf(m, logits[a]);
        float e[NA], se = 0.f;
        #pragma unroll
        for (int a = 0; a < NA; ++a) { e[a] = expf(logits[a] - m); se += e[a]; }
        const float inv = 1.f / se;
        #pragma unroll
        for (int a = 0; a < NA; ++a) out[a] = e[a] * inv;
        out[NA] = logits[NA];
    }
}

extern "C" void kernel_launch(void* const* d_in, const int* in_sizes, int n_in,
                              void* d_out, int out_size)
{
    const float* x      = (const float*)d_in[0];
    const float* hidden = (const float*)d_in[1];
    const float* hebb   = (const float*)d_in[2];
    const float* i2h_w  = (const float*)d_in[3];
    const float* i2h_b  = (const float*)d_in[4];
    const float* w      = (const float*)d_in[5];
    const float* alpha  = (const float*)d_in[6];
    const float* eta    = (const float*)d_in[7];
    const float* h2o_w  = (const float*)d_in[8];
    const float* h2o_b  = (const float*)d_in[9];
    const float* h2v_w  = (const float*)d_in[10];
    const float* h2v_b  = (const float*)d_in[11];
    float* out = (float*)d_out;

    const size_t smem = ((size_t)H * TILE_C + H) * sizeof(float)
                      + 32 * sizeof(float4) + TILE_C * sizeof(float);
    cudaFuncSetAttribute(fused_rnn_kernel,
                         cudaFuncAttributeMaxDynamicSharedMemorySize, (int)smem);

    fused_rnn_kernel<<<H / TILE_C, THREADS, smem>>>(x, hidden, hebb, i2h_w, i2h_b,
                                                    w, alpha, eta, out);
    head_kernel<<<1, 1024>>>(out + 5, h2o_w, h2o_b, h2v_w, h2v_b, out);
}